// round 9
// baseline (speedup 1.0000x reference)
#include <cuda_runtime.h>
#include <cstdint>
#include <cstddef>

#define B_ 2
#define S_ 1024
#define D_ 1024
#define BSD (B_*S_*D_)
#define OUT_ELEMS (B_*S_*D_)                 // 2097152
#define ATTN_ELEMS ((size_t)B_*16*1024*1024) // 33554432

// -------- scratch (static device globals; no runtime allocation) --------
__device__ float g_q[BSD];
__device__ float g_k[BSD];
__device__ float g_v[BSD];
__device__ float g_vt[BSD];
__device__ float g_av[BSD];
__device__ float g_x1[BSD];
__device__ float g_tmp[BSD];
__device__ float g_h1[BSD];
__device__ float g_attn_fb[ATTN_ELEMS];

// ===================== helpers =====================
__device__ __forceinline__ uint32_t tf32r(float x){
    uint32_t y; asm("cvt.rna.tf32.f32 %0, %1;" : "=r"(y) : "f"(x)); return y;
}
__device__ __forceinline__ void tf32split(float x, uint32_t& h, uint32_t& l){
    h = tf32r(x);
    l = tf32r(x - __uint_as_float(h));
}
#define MMA_TF32(d, a0,a1,a2,a3, b0,b1) \
  asm volatile("mma.sync.aligned.m16n8k8.row.col.f32.tf32.tf32.f32 " \
    "{%0,%1,%2,%3}, {%4,%5,%6,%7}, {%8,%9}, {%0,%1,%2,%3};" \
    : "+f"((d)[0]),"+f"((d)[1]),"+f"((d)[2]),"+f"((d)[3]) \
    : "r"(a0),"r"(a1),"r"(a2),"r"(a3),"r"(b0),"r"(b1))

// Row stride in SMEM tiles: 36 words -> bank((4*row+k)) = laneid for both
// A and B fragment loads => conflict-free.
#define SROW 36

// ===================== core mainloop (occupancy-2, single buffer) ==========
// Computes C[128, NT] = A[128, NCHUNK*32] @ B[NT, NCHUNK*32]^T (fp32 via
// 3-pass tf32 split). A and B row stride = 1024 floats.
template<int NT>
__device__ __forceinline__ void stage_tile(
    uint32_t* sm, const float* Ag, const float* Bg,
    int arow, int acol, int brow, int bcol)
{
    constexpr int NB4 = (NT == 128) ? 4 : 2;
    uint32_t* Ah = sm;
    uint32_t* Al = sm + 128*SROW;
    uint32_t* Bh = sm + 2*128*SROW;
    uint32_t* Bl = Bh + NT*SROW;
#pragma unroll
    for (int j = 0; j < 4; j++){
        float4 v = __ldg((const float4*)(Ag + j*4));
        uint4 h, l;
        tf32split(v.x, h.x, l.x);
        tf32split(v.y, h.y, l.y);
        tf32split(v.z, h.z, l.z);
        tf32split(v.w, h.w, l.w);
        *(uint4*)(Ah + arow*SROW + acol + j*4) = h;
        *(uint4*)(Al + arow*SROW + acol + j*4) = l;
    }
#pragma unroll
    for (int j = 0; j < NB4; j++){
        float4 v = __ldg((const float4*)(Bg + j*4));
        uint4 h, l;
        tf32split(v.x, h.x, l.x);
        tf32split(v.y, h.y, l.y);
        tf32split(v.z, h.z, l.z);
        tf32split(v.w, h.w, l.w);
        *(uint4*)(Bh + brow*SROW + bcol + j*4) = h;
        *(uint4*)(Bl + brow*SROW + bcol + j*4) = l;
    }
}

template<int NT>
__device__ __forceinline__ void compute_tile(
    const uint32_t* sm, float (*acc)[4], int lane, int wm, int wn)
{
    constexpr int NTW = NT / 16;
    const uint32_t* Ah = sm;
    const uint32_t* Al = sm + 128*SROW;
    const uint32_t* Bh = sm + 2*128*SROW;
    const uint32_t* Bl = Bh + NT*SROW;
#pragma unroll
    for (int ks = 0; ks < 4; ks++){
        const int kc = ks*8 + (lane & 3);
        uint32_t ah[2][4], al[2][4];
#pragma unroll
        for (int mt = 0; mt < 2; mt++){
            const int r = (wm*32 + mt*16 + (lane >> 2)) * SROW + kc;
            ah[mt][0] = Ah[r];          ah[mt][1] = Ah[r + 8*SROW];
            ah[mt][2] = Ah[r + 4];      ah[mt][3] = Ah[r + 8*SROW + 4];
            al[mt][0] = Al[r];          al[mt][1] = Al[r + 8*SROW];
            al[mt][2] = Al[r + 4];      al[mt][3] = Al[r + 8*SROW + 4];
        }
#pragma unroll
        for (int nt = 0; nt < NTW; nt++){
            const int rb = (wn*(NT/2) + nt*8 + (lane >> 2)) * SROW + kc;
            const uint32_t bh0 = Bh[rb], bh1 = Bh[rb + 4];
            const uint32_t bl0 = Bl[rb], bl1 = Bl[rb + 4];
#pragma unroll
            for (int mt = 0; mt < 2; mt++){
                float* d = acc[mt*NTW + nt];
                MMA_TF32(d, ah[mt][0],ah[mt][1],ah[mt][2],ah[mt][3], bh0,bh1);
                MMA_TF32(d, al[mt][0],al[mt][1],al[mt][2],al[mt][3], bh0,bh1);
                MMA_TF32(d, ah[mt][0],ah[mt][1],ah[mt][2],ah[mt][3], bl0,bl1);
            }
        }
    }
}

template<int NT, int NCHUNK>
__device__ __forceinline__ void mm_loop(
    const float* __restrict__ Abase, const float* __restrict__ Bbase,
    uint32_t* sm, float (*acc)[4], int tid)
{
    const int lane = tid & 31, wid = tid >> 5;
    const int wm = wid & 3, wn = wid >> 2;

    const int arow = tid >> 1, acol = (tid & 1) * 16;
    const int brow = (NT == 128) ? (tid >> 1) : (tid >> 2);
    const int bcol = (NT == 128) ? ((tid & 1) * 16) : ((tid & 3) * 8);

    const float* Ag = Abase + (size_t)arow * 1024 + acol;
    const float* Bg = Bbase + (size_t)brow * 1024 + bcol;

#pragma unroll 1
    for (int i = 0; i < NCHUNK; i++){
        stage_tile<NT>(sm, Ag + i*32, Bg + i*32, arow, acol, brow, bcol);
        __syncthreads();
        compute_tile<NT>(sm, acc, lane, wm, wn);
        __syncthreads();
    }
}

// ===================== kernels =====================
// Dense: C[2048,1024] = A @ W^T (+bias)(+relu)
template<int EP>
__global__ __launch_bounds__(256, 2) void k_dense(
    const float* __restrict__ A, const float* __restrict__ W,
    const float* __restrict__ bias, float* __restrict__ C)
{
    extern __shared__ uint32_t sm[];
    const int tid = threadIdx.x;
    const int m0 = blockIdx.y * 128, n0 = blockIdx.x * 128;
    float acc[16][4];
#pragma unroll
    for (int i = 0; i < 16; i++){ acc[i][0]=0.f; acc[i][1]=0.f; acc[i][2]=0.f; acc[i][3]=0.f; }
    mm_loop<128,32>(A + (size_t)m0*1024, W + (size_t)n0*1024, sm, acc, tid);

    const int lane = tid & 31, wid = tid >> 5;
    const int wm = wid & 3, wn = wid >> 2;
#pragma unroll
    for (int mt = 0; mt < 2; mt++){
#pragma unroll
        for (int nt = 0; nt < 8; nt++){
            const int m = m0 + wm*32 + mt*16 + (lane >> 2);
            const int c = n0 + wn*64 + nt*8 + 2*(lane & 3);
            const float* d = acc[mt*8 + nt];
            float2 lo, hi;
            lo.x = d[0]; lo.y = d[1]; hi.x = d[2]; hi.y = d[3];
            if (EP >= 1){
                float bx = __ldg(bias + c), by = __ldg(bias + c + 1);
                lo.x += bx; lo.y += by; hi.x += bx; hi.y += by;
            }
            if (EP == 2){
                lo.x = fmaxf(lo.x, 0.f); lo.y = fmaxf(lo.y, 0.f);
                hi.x = fmaxf(hi.x, 0.f); hi.y = fmaxf(hi.y, 0.f);
            }
            *(float2*)(C + (size_t)m*1024 + c)       = lo;
            *(float2*)(C + (size_t)(m+8)*1024 + c)   = hi;
        }
    }
}

// QKV fused over blockIdx.z
__global__ __launch_bounds__(256, 2) void k_qkv(
    const float* __restrict__ A,
    const float* __restrict__ Wq, const float* __restrict__ Wk, const float* __restrict__ Wv)
{
    extern __shared__ uint32_t sm[];
    const int tid = threadIdx.x;
    const int m0 = blockIdx.y * 128, n0 = blockIdx.x * 128;
    const int which = blockIdx.z;
    const float* W = (which == 0) ? Wq : (which == 1) ? Wk : Wv;
    float* C = (which == 0) ? g_q : (which == 1) ? g_k : g_v;
    float acc[16][4];
#pragma unroll
    for (int i = 0; i < 16; i++){ acc[i][0]=0.f; acc[i][1]=0.f; acc[i][2]=0.f; acc[i][3]=0.f; }
    mm_loop<128,32>(A + (size_t)m0*1024, W + (size_t)n0*1024, sm, acc, tid);

    const int lane = tid & 31, wid = tid >> 5;
    const int wm = wid & 3, wn = wid >> 2;
#pragma unroll
    for (int mt = 0; mt < 2; mt++){
#pragma unroll
        for (int nt = 0; nt < 8; nt++){
            const int m = m0 + wm*32 + mt*16 + (lane >> 2);
            const int c = n0 + wn*64 + nt*8 + 2*(lane & 3);
            const float* d = acc[mt*8 + nt];
            *(float2*)(C + (size_t)m*1024 + c)     = make_float2(d[0], d[1]);
            *(float2*)(C + (size_t)(m+8)*1024 + c) = make_float2(d[2], d[3]);
        }
    }
}

// Scores: per (b,h) S = Qh @ Kh^T; mask -> -1e12 (pre-scale), then *0.125
__global__ __launch_bounds__(256, 2) void k_scores(
    const int* __restrict__ mask, float* __restrict__ attn)
{
    extern __shared__ uint32_t sm[];
    const int tid = threadIdx.x;
    const int z = blockIdx.z, b = z >> 4, h = z & 15;
    const int m0 = blockIdx.y * 128, n0 = blockIdx.x * 128;
    float acc[16][4];
#pragma unroll
    for (int i = 0; i < 16; i++){ acc[i][0]=0.f; acc[i][1]=0.f; acc[i][2]=0.f; acc[i][3]=0.f; }
    mm_loop<128,2>(g_q + (size_t)b*1048576 + (size_t)m0*1024 + h*64,
                   g_k + (size_t)b*1048576 + (size_t)n0*1024 + h*64,
                   sm, acc, tid);

    const int lane = tid & 31, wid = tid >> 5;
    const int wm = wid & 3, wn = wid >> 2;
    float* Cb = attn + (size_t)z * 1048576;
    const int* mrow = mask + b * 1024;
#pragma unroll
    for (int mt = 0; mt < 2; mt++){
#pragma unroll
        for (int nt = 0; nt < 8; nt++){
            const int m = m0 + wm*32 + mt*16 + (lane >> 2);
            const int c = n0 + wn*64 + nt*8 + 2*(lane & 3);
            const int mk0 = __ldg(mrow + c), mk1 = __ldg(mrow + c + 1);
            const float* d = acc[mt*8 + nt];
            float2 lo, hi;
            lo.x = mk0 ? -1.25e11f : d[0] * 0.125f;
            lo.y = mk1 ? -1.25e11f : d[1] * 0.125f;
            hi.x = mk0 ? -1.25e11f : d[2] * 0.125f;
            hi.y = mk1 ? -1.25e11f : d[3] * 0.125f;
            *(float2*)(Cb + (size_t)m*1024 + c)     = lo;
            *(float2*)(Cb + (size_t)(m+8)*1024 + c) = hi;
        }
    }
}

// AV: per (b,h) av[q, d] = attn[q,:] @ Vt[d,:]  (Vt per-batch transposed V)
__global__ __launch_bounds__(256, 2) void k_av(const float* __restrict__ attn)
{
    extern __shared__ uint32_t sm[];
    const int tid = threadIdx.x;
    const int z = blockIdx.z, b = z >> 4, h = z & 15;
    const int m0 = blockIdx.x * 128;
    float acc[8][4];
#pragma unroll
    for (int i = 0; i < 8; i++){ acc[i][0]=0.f; acc[i][1]=0.f; acc[i][2]=0.f; acc[i][3]=0.f; }
    mm_loop<64,32>(attn + (size_t)z*1048576 + (size_t)m0*1024,
                   g_vt + (size_t)b*1048576 + (size_t)(h*64)*1024,
                   sm, acc, tid);

    const int lane = tid & 31, wid = tid >> 5;
    const int wm = wid & 3, wn = wid >> 2;
#pragma unroll
    for (int mt = 0; mt < 2; mt++){
#pragma unroll
        for (int nt = 0; nt < 4; nt++){
            const int m = m0 + wm*32 + mt*16 + (lane >> 2);
            const int c = wn*32 + nt*8 + 2*(lane & 3);
            const float* d = acc[mt*4 + nt];
            *(float2*)(g_av + (size_t)(b*1024 + m)*1024 + h*64 + c)     = make_float2(d[0], d[1]);
            *(float2*)(g_av + (size_t)(b*1024 + m + 8)*1024 + h*64 + c) = make_float2(d[2], d[3]);
        }
    }
}

// Per-batch 1024x1024 transpose: vt[f][s] = v[s][f]
__global__ __launch_bounds__(256) void k_transpose(
    const float* __restrict__ s, float* __restrict__ d)
{
    __shared__ float t[32][33];
    const int b = blockIdx.z;
    const int x0 = blockIdx.x * 32, y0 = blockIdx.y * 32;
    const float* sp = s + (size_t)b * 1048576;
    float* dp = d + (size_t)b * 1048576;
    const int tx = threadIdx.x & 31, ty = threadIdx.x >> 5;
#pragma unroll
    for (int r = 0; r < 32; r += 8)
        t[ty + r][tx] = sp[(size_t)(y0 + ty + r) * 1024 + x0 + tx];
    __syncthreads();
#pragma unroll
    for (int r = 0; r < 32; r += 8)
        dp[(size_t)(x0 + ty + r) * 1024 + y0 + tx] = t[tx][ty + r];
}

// Row softmax in-place (rows of 1024)
__global__ __launch_bounds__(256) void k_softmax(float* __restrict__ attn)
{
    __shared__ float red[8];
    const int t = threadIdx.x;
    float* p = attn + (size_t)blockIdx.x * 1024 + t * 4;
    float4 v = *(float4*)p;

    float m = fmaxf(fmaxf(v.x, v.y), fmaxf(v.z, v.w));
#pragma unroll
    for (int o = 16; o; o >>= 1) m = fmaxf(m, __shfl_xor_sync(0xffffffffu, m, o));
    if ((t & 31) == 0) red[t >> 5] = m;
    __syncthreads();
    float mx = red[0];
#pragma unroll
    for (int i = 1; i < 8; i++) mx = fmaxf(mx, red[i]);
    __syncthreads();

    float e0 = __expf(v.x - mx), e1 = __expf(v.y - mx), e2 = __expf(v.z - mx), e3 = __expf(v.w - mx);
    float s = e0 + e1 + e2 + e3;
#pragma unroll
    for (int o = 16; o; o >>= 1) s += __shfl_xor_sync(0xffffffffu, s, o);
    if ((t & 31) == 0) red[t >> 5] = s;
    __syncthreads();
    float tot = 0.f;
#pragma unroll
    for (int i = 0; i < 8; i++) tot += red[i];
    float inv = 1.f / tot;

    float4 o4; o4.x = e0 * inv; o4.y = e1 * inv; o4.z = e2 * inv; o4.w = e3 * inv;
    *(float4*)p = o4;
}

// out = LayerNorm(a + r), ddof=1, eps added to std
__global__ __launch_bounds__(256) void k_add_ln(
    const float* __restrict__ a, const float* __restrict__ r,
    const float* __restrict__ gamma, const float* __restrict__ beta,
    float* __restrict__ out)
{
    __shared__ float rs[8];
    __shared__ float rq[8];
    const int t = threadIdx.x;
    const size_t base = (size_t)blockIdx.x * 1024 + t * 4;
    float4 va = *(const float4*)(a + base);
    float4 vr = *(const float4*)(r + base);
    float v0 = va.x + vr.x, v1 = va.y + vr.y, v2 = va.z + vr.z, v3 = va.w + vr.w;

    float s  = v0 + v1 + v2 + v3;
    float sq = v0*v0 + v1*v1 + v2*v2 + v3*v3;
#pragma unroll
    for (int o = 16; o; o >>= 1) {
        s  += __shfl_xor_sync(0xffffffffu, s, o);
        sq += __shfl_xor_sync(0xffffffffu, sq, o);
    }
    if ((t & 31) == 0) { rs[t >> 5] = s; rq[t >> 5] = sq; }
    __syncthreads();
    float S = 0.f, Q = 0.f;
#pragma unroll
    for (int i = 0; i < 8; i++) { S += rs[i]; Q += rq[i]; }

    float mean = S * (1.0f / 1024.0f);
    float var = (Q - 1024.0f * mean * mean) * (1.0f / 1023.0f);
    var = fmaxf(var, 0.f);
    float inv = 1.0f / (sqrtf(var) + 1e-8f);

    float4 g  = *(const float4*)(gamma + t * 4);
    float4 be = *(const float4*)(beta + t * 4);
    float4 o4;
    o4.x = g.x * (v0 - mean) * inv + be.x;
    o4.y = g.y * (v1 - mean) * inv + be.y;
    o4.z = g.z * (v2 - mean) * inv + be.z;
    o4.w = g.w * (v3 - mean) * inv + be.w;
    *(float4*)(out + base) = o4;
}

// =====================================================================
extern "C" void kernel_launch(void* const* d_in, const int* in_sizes, int n_in,
                              void* d_out, int out_size)
{
    const float* x    = (const float*)d_in[0];
    const int*   mask = (const int*)  d_in[1];
    const float* Wq   = (const float*)d_in[2];
    const float* Wk   = (const float*)d_in[3];
    const float* Wv   = (const float*)d_in[4];
    const float* Wo   = (const float*)d_in[5];
    const float* W1   = (const float*)d_in[6];
    const float* b1   = (const float*)d_in[7];
    const float* W2   = (const float*)d_in[8];
    const float* b2   = (const float*)d_in[9];
    const float* g1   = (const float*)d_in[10];
    const float* be1  = (const float*)d_in[11];
    const float* g2   = (const float*)d_in[12];
    const float* be2  = (const float*)d_in[13];

    float *v, *vt, *av, *x1, *tmp, *h1, *afb;
    cudaGetSymbolAddress((void**)&v,   g_v);
    cudaGetSymbolAddress((void**)&vt,  g_vt);
    cudaGetSymbolAddress((void**)&av,  g_av);
    cudaGetSymbolAddress((void**)&x1,  g_x1);
    cudaGetSymbolAddress((void**)&tmp, g_tmp);
    cudaGetSymbolAddress((void**)&h1,  g_h1);
    cudaGetSymbolAddress((void**)&afb, g_attn_fb);

    float* out = (float*)d_out;
    float* attnp = (out_size >= (int)(OUT_ELEMS + ATTN_ELEMS)) ? (out + OUT_ELEMS) : afb;

    const int SM128 = (2*128 + 2*128) * SROW * 4;   // 73728 B (single stage, occ 2)
    const int SM64  = (2*128 + 2*64)  * SROW * 4;   // 55296 B
    cudaFuncSetAttribute(k_qkv,      cudaFuncAttributeMaxDynamicSharedMemorySize, SM128);
    cudaFuncSetAttribute(k_dense<0>, cudaFuncAttributeMaxDynamicSharedMemorySize, SM128);
    cudaFuncSetAttribute(k_dense<1>, cudaFuncAttributeMaxDynamicSharedMemorySize, SM128);
    cudaFuncSetAttribute(k_dense<2>, cudaFuncAttributeMaxDynamicSharedMemorySize, SM128);
    cudaFuncSetAttribute(k_scores,   cudaFuncAttributeMaxDynamicSharedMemorySize, SM128);
    cudaFuncSetAttribute(k_av,       cudaFuncAttributeMaxDynamicSharedMemorySize, SM64);

    k_qkv<<<dim3(8, 16, 3), 256, SM128>>>(x, Wq, Wk, Wv);
    k_transpose<<<dim3(32, 32, 2), 256>>>(v, vt);

    k_scores<<<dim3(8, 8, 32), 256, SM128>>>(mask, attnp);
    k_softmax<<<32768, 256>>>(attnp);
    k_av<<<dim3(8, 1, 32), 256, SM64>>>(attnp);

    k_dense<0><<<dim3(8, 16), 256, SM128>>>(av, Wo, nullptr, tmp);
    k_add_ln<<<2048, 256>>>(x, tmp, g1, be1, x1);

    k_dense<2><<<dim3(8, 16), 256, SM128>>>(x1, W1, b1, h1);
    k_dense<1><<<dim3(8, 16), 256, SM128>>>(h1, W2, b2, tmp);
    k_add_ln<<<2048, 256>>>(x1, tmp, g2, be2, out);
}

// round 10
// speedup vs baseline: 1.4769x; 1.4769x over previous
#include <cuda_runtime.h>
#include <cuda_bf16.h>
#include <cstdint>
#include <cstddef>

#define B_ 2
#define S_ 1024
#define D_ 1024
#define BSD (B_*S_*D_)
#define OUT_ELEMS (B_*S_*D_)                 // 2097152
#define ATTN_ELEMS ((size_t)B_*16*1024*1024) // 33554432

// -------- scratch (static device globals; no runtime allocation) --------
__device__ float g_q[BSD];
__device__ float g_k[BSD];
__device__ float g_v[BSD];
__device__ float g_vt[BSD];
__device__ float g_av[BSD];
__device__ float g_x1[BSD];
__device__ float g_tmp[BSD];
__device__ float g_h1[BSD];
__device__ float g_attn_fb[ATTN_ELEMS];

// ===================== helpers =====================
// Split float pair into bf16x2 hi + bf16x2 lo (residual). Dropped error ~2^-18.
__device__ __forceinline__ void bfsplit2(float a, float b, uint32_t& h, uint32_t& l){
    __nv_bfloat162 h2 = __floats2bfloat162_rn(a, b);
    float ra = a - __low2float(h2);
    float rb = b - __high2float(h2);
    __nv_bfloat162 l2 = __floats2bfloat162_rn(ra, rb);
    h = *reinterpret_cast<uint32_t*>(&h2);
    l = *reinterpret_cast<uint32_t*>(&l2);
}
#define MMA_BF16(d, a0,a1,a2,a3, b0,b1) \
  asm volatile("mma.sync.aligned.m16n8k16.row.col.f32.bf16.bf16.f32 " \
    "{%0,%1,%2,%3}, {%4,%5,%6,%7}, {%8,%9}, {%0,%1,%2,%3};" \
    : "+f"((d)[0]),"+f"((d)[1]),"+f"((d)[2]),"+f"((d)[3]) \
    : "r"(a0),"r"(a1),"r"(a2),"r"(a3),"r"(b0),"r"(b1))

// Row stride in SMEM tiles: 20 words (16 data + 4 pad). Fragment loads
// (words t, t+4, rows g/g+8) hit all-distinct banks across the warp.
#define SROWB 20

// ===================== core mainloop (double-buffered, bf16x3) =============
// Computes C[128, NT] = A[128, NCHUNK*32] @ B[NT, NCHUNK*32]^T (fp32 via
// 3-pass bf16 split). A and B row stride = 1024 floats.
// SMEM stage layout (32-bit words, each = bf16x2): Ah[128*20] Al[128*20]
// Bh[NT*20] Bl[NT*20].
template<int NT>
__device__ __forceinline__ void stage_tile(
    uint32_t* sm, const float4* pa, const float4* pb, int tid)
{
    constexpr int NB4 = (NT == 128) ? 4 : 2;
    uint32_t* Ah = sm;
    uint32_t* Al = sm + 128*SROWB;
    uint32_t* Bh = sm + 2*128*SROWB;
    uint32_t* Bl = Bh + NT*SROWB;
    const int arow = tid >> 1;
    const int aw0  = (tid & 1) * 8;           // word offset within row
    const int brow = (NT == 128) ? (tid >> 1) : (tid >> 2);
    const int bw0  = (NT == 128) ? ((tid & 1) * 8) : ((tid & 3) * 4);
#pragma unroll
    for (int j = 0; j < 4; j++){
        uint32_t h0, l0, h1, l1;
        bfsplit2(pa[j].x, pa[j].y, h0, l0);
        bfsplit2(pa[j].z, pa[j].w, h1, l1);
        const int w = arow*SROWB + aw0 + j*2;
        *(uint2*)(Ah + w) = make_uint2(h0, h1);
        *(uint2*)(Al + w) = make_uint2(l0, l1);
    }
#pragma unroll
    for (int j = 0; j < NB4; j++){
        uint32_t h0, l0, h1, l1;
        bfsplit2(pb[j].x, pb[j].y, h0, l0);
        bfsplit2(pb[j].z, pb[j].w, h1, l1);
        const int w = brow*SROWB + bw0 + j*2;
        *(uint2*)(Bh + w) = make_uint2(h0, h1);
        *(uint2*)(Bl + w) = make_uint2(l0, l1);
    }
}

template<int NT>
__device__ __forceinline__ void compute_tile(
    const uint32_t* sm, float (*acc)[4], int lane, int wm, int wn)
{
    constexpr int NTW = NT / 16;
    const uint32_t* Ah = sm;
    const uint32_t* Al = sm + 128*SROWB;
    const uint32_t* Bh = sm + 2*128*SROWB;
    const uint32_t* Bl = Bh + NT*SROWB;
    const int g = lane >> 2, t = lane & 3;
#pragma unroll
    for (int ks = 0; ks < 2; ks++){
        const int wb = ks*8 + t;
        uint32_t ah[2][4], al[2][4];
#pragma unroll
        for (int mt = 0; mt < 2; mt++){
            const int r = (wm*32 + mt*16 + g) * SROWB + wb;
            ah[mt][0] = Ah[r];              ah[mt][1] = Ah[r + 8*SROWB];
            ah[mt][2] = Ah[r + 4];          ah[mt][3] = Ah[r + 8*SROWB + 4];
            al[mt][0] = Al[r];              al[mt][1] = Al[r + 8*SROWB];
            al[mt][2] = Al[r + 4];          al[mt][3] = Al[r + 8*SROWB + 4];
        }
#pragma unroll
        for (int nt = 0; nt < NTW; nt++){
            const int rb = (wn*(NT/2) + nt*8 + g) * SROWB + wb;
            const uint32_t bh0 = Bh[rb], bh1 = Bh[rb + 4];
            const uint32_t bl0 = Bl[rb], bl1 = Bl[rb + 4];
#pragma unroll
            for (int mt = 0; mt < 2; mt++){
                float* d = acc[mt*NTW + nt];
                MMA_BF16(d, ah[mt][0],ah[mt][1],ah[mt][2],ah[mt][3], bh0,bh1);
                MMA_BF16(d, al[mt][0],al[mt][1],al[mt][2],al[mt][3], bh0,bh1);
                MMA_BF16(d, ah[mt][0],ah[mt][1],ah[mt][2],ah[mt][3], bl0,bl1);
            }
        }
    }
}

template<int NT, int NCHUNK>
__device__ __forceinline__ void mm_loop(
    const float* __restrict__ Abase, const float* __restrict__ Bbase,
    uint32_t* sm, float (*acc)[4], int tid)
{
    constexpr int NB4 = (NT == 128) ? 4 : 2;
    constexpr int BUF = (2*128 + 2*NT) * SROWB;   // words per stage
    const int lane = tid & 31, wid = tid >> 5;
    const int wm = wid & 3, wn = wid >> 2;

    const int arow = tid >> 1, acol = (tid & 1) * 16;
    const int brow = (NT == 128) ? (tid >> 1) : (tid >> 2);
    const int bcol = (NT == 128) ? ((tid & 1) * 16) : ((tid & 3) * 8);

    const float* Ag = Abase + (size_t)arow * 1024 + acol;
    const float* Bg = Bbase + (size_t)brow * 1024 + bcol;

    float4 pa[4], pb[NB4];
#pragma unroll
    for (int j = 0; j < 4;   j++) pa[j] = __ldg((const float4*)(Ag + j*4));
#pragma unroll
    for (int j = 0; j < NB4; j++) pb[j] = __ldg((const float4*)(Bg + j*4));

    stage_tile<NT>(sm, pa, pb, tid);
    __syncthreads();

#pragma unroll 1
    for (int i = 0; i < NCHUNK; i++){
        if (i + 1 < NCHUNK){
            const float* a = Ag + (i+1)*32;
            const float* b = Bg + (i+1)*32;
#pragma unroll
            for (int j = 0; j < 4;   j++) pa[j] = __ldg((const float4*)(a + j*4));
#pragma unroll
            for (int j = 0; j < NB4; j++) pb[j] = __ldg((const float4*)(b + j*4));
        }
        compute_tile<NT>(sm + (i & 1)*BUF, acc, lane, wm, wn);
        if (i + 1 < NCHUNK)
            stage_tile<NT>(sm + ((i+1) & 1)*BUF, pa, pb, tid);
        __syncthreads();
    }
}

// ===================== kernels =====================
// Dense: C[2048,1024] = A @ W^T (+bias)(+relu)
template<int EP>
__global__ __launch_bounds__(256, 1) void k_dense(
    const float* __restrict__ A, const float* __restrict__ W,
    const float* __restrict__ bias, float* __restrict__ C)
{
    extern __shared__ uint32_t sm[];
    const int tid = threadIdx.x;
    const int m0 = blockIdx.y * 128, n0 = blockIdx.x * 128;
    float acc[16][4];
#pragma unroll
    for (int i = 0; i < 16; i++){ acc[i][0]=0.f; acc[i][1]=0.f; acc[i][2]=0.f; acc[i][3]=0.f; }
    mm_loop<128,32>(A + (size_t)m0*1024, W + (size_t)n0*1024, sm, acc, tid);

    const int lane = tid & 31, wid = tid >> 5;
    const int wm = wid & 3, wn = wid >> 2;
#pragma unroll
    for (int mt = 0; mt < 2; mt++){
#pragma unroll
        for (int nt = 0; nt < 8; nt++){
            const int m = m0 + wm*32 + mt*16 + (lane >> 2);
            const int c = n0 + wn*64 + nt*8 + 2*(lane & 3);
            const float* d = acc[mt*8 + nt];
            float2 lo, hi;
            lo.x = d[0]; lo.y = d[1]; hi.x = d[2]; hi.y = d[3];
            if (EP >= 1){
                float bx = __ldg(bias + c), by = __ldg(bias + c + 1);
                lo.x += bx; lo.y += by; hi.x += bx; hi.y += by;
            }
            if (EP == 2){
                lo.x = fmaxf(lo.x, 0.f); lo.y = fmaxf(lo.y, 0.f);
                hi.x = fmaxf(hi.x, 0.f); hi.y = fmaxf(hi.y, 0.f);
            }
            *(float2*)(C + (size_t)m*1024 + c)       = lo;
            *(float2*)(C + (size_t)(m+8)*1024 + c)   = hi;
        }
    }
}

// QKV fused over blockIdx.z
__global__ __launch_bounds__(256, 1) void k_qkv(
    const float* __restrict__ A,
    const float* __restrict__ Wq, const float* __restrict__ Wk, const float* __restrict__ Wv)
{
    extern __shared__ uint32_t sm[];
    const int tid = threadIdx.x;
    const int m0 = blockIdx.y * 128, n0 = blockIdx.x * 128;
    const int which = blockIdx.z;
    const float* W = (which == 0) ? Wq : (which == 1) ? Wk : Wv;
    float* C = (which == 0) ? g_q : (which == 1) ? g_k : g_v;
    float acc[16][4];
#pragma unroll
    for (int i = 0; i < 16; i++){ acc[i][0]=0.f; acc[i][1]=0.f; acc[i][2]=0.f; acc[i][3]=0.f; }
    mm_loop<128,32>(A + (size_t)m0*1024, W + (size_t)n0*1024, sm, acc, tid);

    const int lane = tid & 31, wid = tid >> 5;
    const int wm = wid & 3, wn = wid >> 2;
#pragma unroll
    for (int mt = 0; mt < 2; mt++){
#pragma unroll
        for (int nt = 0; nt < 8; nt++){
            const int m = m0 + wm*32 + mt*16 + (lane >> 2);
            const int c = n0 + wn*64 + nt*8 + 2*(lane & 3);
            const float* d = acc[mt*8 + nt];
            *(float2*)(C + (size_t)m*1024 + c)     = make_float2(d[0], d[1]);
            *(float2*)(C + (size_t)(m+8)*1024 + c) = make_float2(d[2], d[3]);
        }
    }
}

// Scores: per (b,h) S = Qh @ Kh^T; mask -> -1e12 (pre-scale), then *0.125
__global__ __launch_bounds__(256, 1) void k_scores(
    const int* __restrict__ mask, float* __restrict__ attn)
{
    extern __shared__ uint32_t sm[];
    const int tid = threadIdx.x;
    const int z = blockIdx.z, b = z >> 4, h = z & 15;
    const int m0 = blockIdx.y * 128, n0 = blockIdx.x * 128;
    float acc[16][4];
#pragma unroll
    for (int i = 0; i < 16; i++){ acc[i][0]=0.f; acc[i][1]=0.f; acc[i][2]=0.f; acc[i][3]=0.f; }
    mm_loop<128,2>(g_q + (size_t)b*1048576 + (size_t)m0*1024 + h*64,
                   g_k + (size_t)b*1048576 + (size_t)n0*1024 + h*64,
                   sm, acc, tid);

    const int lane = tid & 31, wid = tid >> 5;
    const int wm = wid & 3, wn = wid >> 2;
    float* Cb = attn + (size_t)z * 1048576;
    const int* mrow = mask + b * 1024;
#pragma unroll
    for (int mt = 0; mt < 2; mt++){
#pragma unroll
        for (int nt = 0; nt < 8; nt++){
            const int m = m0 + wm*32 + mt*16 + (lane >> 2);
            const int c = n0 + wn*64 + nt*8 + 2*(lane & 3);
            const int mk0 = __ldg(mrow + c), mk1 = __ldg(mrow + c + 1);
            const float* d = acc[mt*8 + nt];
            float2 lo, hi;
            lo.x = mk0 ? -1.25e11f : d[0] * 0.125f;
            lo.y = mk1 ? -1.25e11f : d[1] * 0.125f;
            hi.x = mk0 ? -1.25e11f : d[2] * 0.125f;
            hi.y = mk1 ? -1.25e11f : d[3] * 0.125f;
            *(float2*)(Cb + (size_t)m*1024 + c)     = lo;
            *(float2*)(Cb + (size_t)(m+8)*1024 + c) = hi;
        }
    }
}

// AV: per (b,h) av[q, d] = attn[q,:] @ Vt[d,:]  (Vt per-batch transposed V)
__global__ __launch_bounds__(256, 1) void k_av(const float* __restrict__ attn)
{
    extern __shared__ uint32_t sm[];
    const int tid = threadIdx.x;
    const int z = blockIdx.z, b = z >> 4, h = z & 15;
    const int m0 = blockIdx.x * 128;
    float acc[8][4];
#pragma unroll
    for (int i = 0; i < 8; i++){ acc[i][0]=0.f; acc[i][1]=0.f; acc[i][2]=0.f; acc[i][3]=0.f; }
    mm_loop<64,32>(attn + (size_t)z*1048576 + (size_t)m0*1024,
                   g_vt + (size_t)b*1048576 + (size_t)(h*64)*1024,
                   sm, acc, tid);

    const int lane = tid & 31, wid = tid >> 5;
    const int wm = wid & 3, wn = wid >> 2;
#pragma unroll
    for (int mt = 0; mt < 2; mt++){
#pragma unroll
        for (int nt = 0; nt < 4; nt++){
            const int m = m0 + wm*32 + mt*16 + (lane >> 2);
            const int c = wn*32 + nt*8 + 2*(lane & 3);
            const float* d = acc[mt*4 + nt];
            *(float2*)(g_av + (size_t)(b*1024 + m)*1024 + h*64 + c)     = make_float2(d[0], d[1]);
            *(float2*)(g_av + (size_t)(b*1024 + m + 8)*1024 + h*64 + c) = make_float2(d[2], d[3]);
        }
    }
}

// Per-batch 1024x1024 transpose: vt[f][s] = v[s][f]
__global__ __launch_bounds__(256) void k_transpose(
    const float* __restrict__ s, float* __restrict__ d)
{
    __shared__ float t[32][33];
    const int b = blockIdx.z;
    const int x0 = blockIdx.x * 32, y0 = blockIdx.y * 32;
    const float* sp = s + (size_t)b * 1048576;
    float* dp = d + (size_t)b * 1048576;
    const int tx = threadIdx.x & 31, ty = threadIdx.x >> 5;
#pragma unroll
    for (int r = 0; r < 32; r += 8)
        t[ty + r][tx] = sp[(size_t)(y0 + ty + r) * 1024 + x0 + tx];
    __syncthreads();
#pragma unroll
    for (int r = 0; r < 32; r += 8)
        dp[(size_t)(x0 + ty + r) * 1024 + y0 + tx] = t[tx][ty + r];
}

// Row softmax in-place (rows of 1024)
__global__ __launch_bounds__(256) void k_softmax(float* __restrict__ attn)
{
    __shared__ float red[8];
    const int t = threadIdx.x;
    float* p = attn + (size_t)blockIdx.x * 1024 + t * 4;
    float4 v = *(float4*)p;

    float m = fmaxf(fmaxf(v.x, v.y), fmaxf(v.z, v.w));
#pragma unroll
    for (int o = 16; o; o >>= 1) m = fmaxf(m, __shfl_xor_sync(0xffffffffu, m, o));
    if ((t & 31) == 0) red[t >> 5] = m;
    __syncthreads();
    float mx = red[0];
#pragma unroll
    for (int i = 1; i < 8; i++) mx = fmaxf(mx, red[i]);
    __syncthreads();

    float e0 = __expf(v.x - mx), e1 = __expf(v.y - mx), e2 = __expf(v.z - mx), e3 = __expf(v.w - mx);
    float s = e0 + e1 + e2 + e3;
#pragma unroll
    for (int o = 16; o; o >>= 1) s += __shfl_xor_sync(0xffffffffu, s, o);
    if ((t & 31) == 0) red[t >> 5] = s;
    __syncthreads();
    float tot = 0.f;
#pragma unroll
    for (int i = 0; i < 8; i++) tot += red[i];
    float inv = 1.f / tot;

    float4 o4; o4.x = e0 * inv; o4.y = e1 * inv; o4.z = e2 * inv; o4.w = e3 * inv;
    *(float4*)p = o4;
}

// out = LayerNorm(a + r), ddof=1, eps added to std
__global__ __launch_bounds__(256) void k_add_ln(
    const float* __restrict__ a, const float* __restrict__ r,
    const float* __restrict__ gamma, const float* __restrict__ beta,
    float* __restrict__ out)
{
    __shared__ float rs[8];
    __shared__ float rq[8];
    const int t = threadIdx.x;
    const size_t base = (size_t)blockIdx.x * 1024 + t * 4;
    float4 va = *(const float4*)(a + base);
    float4 vr = *(const float4*)(r + base);
    float v0 = va.x + vr.x, v1 = va.y + vr.y, v2 = va.z + vr.z, v3 = va.w + vr.w;

    float s  = v0 + v1 + v2 + v3;
    float sq = v0*v0 + v1*v1 + v2*v2 + v3*v3;
#pragma unroll
    for (int o = 16; o; o >>= 1) {
        s  += __shfl_xor_sync(0xffffffffu, s, o);
        sq += __shfl_xor_sync(0xffffffffu, sq, o);
    }
    if ((t & 31) == 0) { rs[t >> 5] = s; rq[t >> 5] = sq; }
    __syncthreads();
    float S = 0.f, Q = 0.f;
#pragma unroll
    for (int i = 0; i < 8; i++) { S += rs[i]; Q += rq[i]; }

    float mean = S * (1.0f / 1024.0f);
    float var = (Q - 1024.0f * mean * mean) * (1.0f / 1023.0f);
    var = fmaxf(var, 0.f);
    float inv = 1.0f / (sqrtf(var) + 1e-8f);

    float4 g  = *(const float4*)(gamma + t * 4);
    float4 be = *(const float4*)(beta + t * 4);
    float4 o4;
    o4.x = g.x * (v0 - mean) * inv + be.x;
    o4.y = g.y * (v1 - mean) * inv + be.y;
    o4.z = g.z * (v2 - mean) * inv + be.z;
    o4.w = g.w * (v3 - mean) * inv + be.w;
    *(float4*)(out + base) = o4;
}

// =====================================================================
extern "C" void kernel_launch(void* const* d_in, const int* in_sizes, int n_in,
                              void* d_out, int out_size)
{
    const float* x    = (const float*)d_in[0];
    const int*   mask = (const int*)  d_in[1];
    const float* Wq   = (const float*)d_in[2];
    const float* Wk   = (const float*)d_in[3];
    const float* Wv   = (const float*)d_in[4];
    const float* Wo   = (const float*)d_in[5];
    const float* W1   = (const float*)d_in[6];
    const float* b1   = (const float*)d_in[7];
    const float* W2   = (const float*)d_in[8];
    const float* b2   = (const float*)d_in[9];
    const float* g1   = (const float*)d_in[10];
    const float* be1  = (const float*)d_in[11];
    const float* g2   = (const float*)d_in[12];
    const float* be2  = (const float*)d_in[13];

    float *v, *vt, *av, *x1, *tmp, *h1, *afb;
    cudaGetSymbolAddress((void**)&v,   g_v);
    cudaGetSymbolAddress((void**)&vt,  g_vt);
    cudaGetSymbolAddress((void**)&av,  g_av);
    cudaGetSymbolAddress((void**)&x1,  g_x1);
    cudaGetSymbolAddress((void**)&tmp, g_tmp);
    cudaGetSymbolAddress((void**)&h1,  g_h1);
    cudaGetSymbolAddress((void**)&afb, g_attn_fb);

    float* out = (float*)d_out;
    float* attnp = (out_size >= (int)(OUT_ELEMS + ATTN_ELEMS)) ? (out + OUT_ELEMS) : afb;

    const int SM128 = 2 * (2*128 + 2*128) * SROWB * 4;   // 81920 B (double-buffered)
    const int SM64  = 2 * (2*128 + 2*64)  * SROWB * 4;   // 61440 B
    cudaFuncSetAttribute(k_qkv,      cudaFuncAttributeMaxDynamicSharedMemorySize, SM128);
    cudaFuncSetAttribute(k_dense<0>, cudaFuncAttributeMaxDynamicSharedMemorySize, SM128);
    cudaFuncSetAttribute(k_dense<1>, cudaFuncAttributeMaxDynamicSharedMemorySize, SM128);
    cudaFuncSetAttribute(k_dense<2>, cudaFuncAttributeMaxDynamicSharedMemorySize, SM128);
    cudaFuncSetAttribute(k_scores,   cudaFuncAttributeMaxDynamicSharedMemorySize, SM128);
    cudaFuncSetAttribute(k_av,       cudaFuncAttributeMaxDynamicSharedMemorySize, SM64);

    k_qkv<<<dim3(8, 16, 3), 256, SM128>>>(x, Wq, Wk, Wv);
    k_transpose<<<dim3(32, 32, 2), 256>>>(v, vt);

    k_scores<<<dim3(8, 8, 32), 256, SM128>>>(mask, attnp);
    k_softmax<<<32768, 256>>>(attnp);
    k_av<<<dim3(8, 1, 32), 256, SM64>>>(attnp);

    k_dense<0><<<dim3(8, 16), 256, SM128>>>(av, Wo, nullptr, tmp);
    k_add_ln<<<2048, 256>>>(x, tmp, g1, be1, x1);

    k_dense<2><<<dim3(8, 16), 256, SM128>>>(x1, W1, b1, h1);
    k_dense<1><<<dim3(8, 16), 256, SM128>>>(h1, W2, b2, tmp);
    k_add_ln<<<2048, 256>>>(x1, tmp, g2, be2, out);
}